// round 3
// baseline (speedup 1.0000x reference)
#include <cuda_runtime.h>
#include <cstdint>
#include <math.h>

#define D_MODEL 1024
#define FF      4096
#define NE      8
#define S_TOK   8192
#define CAP     1280   // int(1.25 * 8192 / 8)

// ---------------- scratch (device globals; no allocation allowed) ----------------
__device__ float d_xin [NE * CAP * D_MODEL];   // gathered expert inputs
__device__ float d_h   [NE * CAP * FF];        // hidden activations
__device__ float d_eout[NE * CAP * D_MODEL];   // expert outputs
__device__ int   d_idxbuf[NE * CAP];           // slot -> token
__device__ int   d_counts[NE];                 // per-expert filled slots (<= CAP)
__device__ int   d_slot [S_TOK * 2];           // (token,k) -> global slot or -1
__device__ float d_w    [S_TOK * 2];           // (token,k) -> normalized weight
__device__ int   d_top2 [S_TOK * 2];           // (token,k) -> expert id

// ---------------- helpers ----------------
__device__ __forceinline__ float to_tf32(float x) {
    float r;
    asm("cvt.rna.tf32.f32 %0, %1;" : "=f"(r) : "f"(x));
    return r;
}
__device__ __forceinline__ uint32_t to_tf32_u(float x) {
    return __float_as_uint(to_tf32(x));
}

__device__ __forceinline__ void cp_async16(void* smem_dst, const void* gmem_src) {
    uint32_t s = (uint32_t)__cvta_generic_to_shared(smem_dst);
    asm volatile("cp.async.cg.shared.global [%0], [%1], 16;\n" :: "r"(s), "l"(gmem_src));
}
#define CP_COMMIT()  asm volatile("cp.async.commit_group;\n" ::: "memory")
#define CP_WAIT(n)   asm volatile("cp.async.wait_group %0;\n" :: "n"(n) : "memory")

#define MMA_TF32(c, a, b)                                                        \
    asm volatile(                                                                \
        "mma.sync.aligned.m16n8k8.row.col.f32.tf32.tf32.f32 "                    \
        "{%0,%1,%2,%3},{%4,%5,%6,%7},{%8,%9},{%0,%1,%2,%3};\n"                   \
        : "+f"((c)[0]), "+f"((c)[1]), "+f"((c)[2]), "+f"((c)[3])                 \
        : "r"((a)[0]), "r"((a)[1]), "r"((a)[2]), "r"((a)[3]),                    \
          "r"((b)[0]), "r"((b)[1]))

// ---------------- 1) gating: logits -> top2 + normalized weights ----------------
// one warp per token, 8 tokens per 256-thread block
__global__ __launch_bounds__(256) void gating_kernel(
    const float* __restrict__ x, const float* __restrict__ gw,
    const float* __restrict__ gb)
{
    __shared__ float sgw[D_MODEL * NE];   // 32 KB
    for (int i = threadIdx.x; i < D_MODEL * NE; i += 256) sgw[i] = gw[i];
    __syncthreads();

    int wid = threadIdx.x >> 5, lane = threadIdx.x & 31;
    int t = blockIdx.x * 8 + wid;
    const float* xr = x + (size_t)t * D_MODEL;

    float acc[NE];
#pragma unroll
    for (int e = 0; e < NE; e++) acc[e] = 0.f;

    for (int j = lane; j < D_MODEL; j += 32) {
        float xv = xr[j];
#pragma unroll
        for (int e = 0; e < NE; e++) acc[e] += xv * sgw[j * NE + e];
    }
#pragma unroll
    for (int off = 16; off; off >>= 1) {
#pragma unroll
        for (int e = 0; e < NE; e++)
            acc[e] += __shfl_xor_sync(0xffffffffu, acc[e], off);
    }
    if (lane == 0) {
        float l0 = -1e30f, l1 = -1e30f;
        int e0 = 0, e1 = 0;
#pragma unroll
        for (int e = 0; e < NE; e++) {
            float l = acc[e] + gb[e];
            if (l > l0)      { l1 = l0; e1 = e0; l0 = l; e0 = e; }
            else if (l > l1) { l1 = l;  e1 = e; }
        }
        // normalized top-2 softmax weights: w0 = 1/(1+e^{l1-l0})
        float w0 = 1.0f / (1.0f + expf(l1 - l0));
        d_top2[2 * t]     = e0;
        d_top2[2 * t + 1] = e1;
        d_w[2 * t]     = w0;
        d_w[2 * t + 1] = 1.0f - w0;
    }
}

// ---------------- 2) routing: exact per-expert prefix count (token order) ------
// single block, 1024 threads, 8 chunks of 1024 tokens.
// 8 per-expert counters packed as 2x u64 of 4x16-bit lanes (max 1024/chunk fits).
__global__ __launch_bounds__(1024) void route_kernel()
{
    __shared__ unsigned long long wt0[32], wt1[32];
    __shared__ int base[NE];
    __shared__ unsigned long long ct0, ct1;

    int tid = threadIdx.x, lane = tid & 31, wid = tid >> 5;
    if (tid < NE) base[tid] = 0;
    __syncthreads();

    for (int chunk = 0; chunk < S_TOK / 1024; chunk++) {
        int t  = chunk * 1024 + tid;
        int e0 = d_top2[2 * t], e1 = d_top2[2 * t + 1];

        unsigned long long v0 = 0, v1 = 0;
        {
            unsigned long long inc = 1ull << ((e0 & 3) * 16);
            if (e0 < 4) v0 += inc; else v1 += inc;
        }
        {
            unsigned long long inc = 1ull << ((e1 & 3) * 16);
            if (e1 < 4) v0 += inc; else v1 += inc;
        }

        // warp inclusive scan
        unsigned long long p0 = v0, p1 = v1;
#pragma unroll
        for (int off = 1; off < 32; off <<= 1) {
            unsigned long long u0 = __shfl_up_sync(0xffffffffu, p0, off);
            unsigned long long u1 = __shfl_up_sync(0xffffffffu, p1, off);
            if (lane >= off) { p0 += u0; p1 += u1; }
        }
        if (lane == 31) { wt0[wid] = p0; wt1[wid] = p1; }
        __syncthreads();

        // warp 0 scans warp totals
        if (wid == 0) {
            unsigned long long q0 = wt0[lane], q1 = wt1[lane];
#pragma unroll
            for (int off = 1; off < 32; off <<= 1) {
                unsigned long long u0 = __shfl_up_sync(0xffffffffu, q0, off);
                unsigned long long u1 = __shfl_up_sync(0xffffffffu, q1, off);
                if (lane >= off) { q0 += u0; q1 += u1; }
            }
            wt0[lane] = q0; wt1[lane] = q1;
            if (lane == 31) { ct0 = q0; ct1 = q1; }
        }
        __syncthreads();

        unsigned long long ex0 = p0 - v0, ex1 = p1 - v1;  // exclusive within warp
        if (wid > 0) { ex0 += wt0[wid - 1]; ex1 += wt1[wid - 1]; }

#pragma unroll
        for (int k = 0; k < 2; k++) {
            int e = (k == 0) ? e0 : e1;
            unsigned long long ex = (e < 4) ? ex0 : ex1;
            int within = (int)((ex >> ((e & 3) * 16)) & 0xFFFFu);
            int pos = base[e] + within;
            int slot;
            if (pos < CAP) {
                slot = e * CAP + pos;
                d_idxbuf[slot] = t;
            } else {
                slot = -1;
            }
            d_slot[2 * t + k] = slot;
        }
        __syncthreads();
        if (tid < NE) {
            unsigned long long cv = (tid < 4) ? ct0 : ct1;
            base[tid] += (int)((cv >> ((tid & 3) * 16)) & 0xFFFFu);
        }
        __syncthreads();
    }
    if (threadIdx.x < NE)
        d_counts[threadIdx.x] = min(base[threadIdx.x], CAP);
}

// ---------------- 3) gather expert inputs (zero unfilled slots) ----------------
// one block per slot row, 256 threads x float4 = 1024 floats
__global__ __launch_bounds__(256) void gather_kernel(const float* __restrict__ x)
{
    int row = blockIdx.x;                 // 0 .. NE*CAP-1
    int e = row / CAP, c = row - e * CAP;
    float4 v = make_float4(0.f, 0.f, 0.f, 0.f);
    if (c < d_counts[e]) {
        int tok = d_idxbuf[row];
        v = *reinterpret_cast<const float4*>(
            &x[(size_t)tok * D_MODEL + threadIdx.x * 4]);
    }
    *reinterpret_cast<float4*>(
        &d_xin[(size_t)row * D_MODEL + threadIdx.x * 4]) = v;
}

// ---------------- 4/5) batched TF32 GEMM core, cp.async double-buffered --------
// C[M,N] = A[M,K] @ B[K,N] (+bias[N]) (+ReLU). Tiles: 128x64x16, 8 warps,
// warp tile 32x32 = 2x4 m16n8k8 mma per k-step, two k-steps per tile.
template <int M, int N, int K, bool RELU>
__device__ __forceinline__ void gemm_core(
    const float* __restrict__ A, const float* __restrict__ Bw,
    const float* __restrict__ bias, float* __restrict__ Cout)
{
    constexpr int BM = 128, BN = 64, BK = 16;
    constexpr int ASTR = BK + 4;   // 20: frag banks (gid*20+tig)%32 all distinct
    constexpr int BSTR = BN + 8;   // 72: frag banks (tig*8+gid)%32 all distinct
    __shared__ float As[2][BM][ASTR];   // 2 * 128*20*4 = 20.0 KB
    __shared__ float Bs[2][BK][BSTR];   // 2 * 16*72*4  =  9.0 KB

    const int tid = threadIdx.x;
    const int wid = tid >> 5, lane = tid & 31;
    const int gid = lane >> 2, tig = lane & 3;
    const int wm = (wid >> 1) * 32;    // warp m offset (0,32,64,96)
    const int wn = (wid & 1) * 32;     // warp n offset (0,32)
    const int m0 = blockIdx.y * BM;
    const int n0 = blockIdx.x * BN;

    // per-thread copy coordinates
    const int a_row0 = tid >> 2;            // 0..63   (chunk r adds 64)
    const int a_col  = (tid & 3) * 4;       // 0,4,8,12
    const int b_row  = tid >> 4;            // 0..15
    const int b_col  = (tid & 15) * 4;      // 0..60

    auto load_tile = [&](int buf, int k0) {
#pragma unroll
        for (int r = 0; r < 2; r++) {
            int row = a_row0 + r * 64;
            cp_async16(&As[buf][row][a_col],
                       &A[(size_t)(m0 + row) * K + k0 + a_col]);
        }
        cp_async16(&Bs[buf][b_row][b_col],
                   &Bw[(size_t)(k0 + b_row) * N + n0 + b_col]);
        CP_COMMIT();
    };

    float c[2][4][4];
#pragma unroll
    for (int mt = 0; mt < 2; mt++)
#pragma unroll
        for (int nt = 0; nt < 4; nt++)
#pragma unroll
            for (int i = 0; i < 4; i++) c[mt][nt][i] = 0.f;

    constexpr int NK = K / BK;
    load_tile(0, 0);

    for (int kt = 0; kt < NK; kt++) {
        const int buf = kt & 1;
        if (kt + 1 < NK) {
            load_tile(buf ^ 1, (kt + 1) * BK);
            CP_WAIT(1);
        } else {
            CP_WAIT(0);
        }
        __syncthreads();

#pragma unroll
        for (int kk = 0; kk < BK; kk += 8) {
            uint32_t a[2][4], b[4][2];
#pragma unroll
            for (int mt = 0; mt < 2; mt++) {
                int rb = wm + mt * 16;
                a[mt][0] = to_tf32_u(As[buf][rb + gid     ][kk + tig]);
                a[mt][1] = to_tf32_u(As[buf][rb + gid + 8 ][kk + tig]);
                a[mt][2] = to_tf32_u(As[buf][rb + gid     ][kk + tig + 4]);
                a[mt][3] = to_tf32_u(As[buf][rb + gid + 8 ][kk + tig + 4]);
            }
#pragma unroll
            for (int nt = 0; nt < 4; nt++) {
                int cb = wn + nt * 8;
                b[nt][0] = to_tf32_u(Bs[buf][kk + tig    ][cb + gid]);
                b[nt][1] = to_tf32_u(Bs[buf][kk + tig + 4][cb + gid]);
            }
#pragma unroll
            for (int mt = 0; mt < 2; mt++)
#pragma unroll
                for (int nt = 0; nt < 4; nt++)
                    MMA_TF32(c[mt][nt], a[mt], b[nt]);
        }
        __syncthreads();
    }

    // epilogue: +bias, optional relu, float2 stores
#pragma unroll
    for (int mt = 0; mt < 2; mt++) {
#pragma unroll
        for (int nt = 0; nt < 4; nt++) {
            int row = m0 + wm + mt * 16 + gid;
            int col = n0 + wn + nt * 8 + tig * 2;
            float b0v = bias[col], b1v = bias[col + 1];
            float v0 = c[mt][nt][0] + b0v;
            float v1 = c[mt][nt][1] + b1v;
            float v2 = c[mt][nt][2] + b0v;
            float v3 = c[mt][nt][3] + b1v;
            if (RELU) {
                v0 = fmaxf(v0, 0.f); v1 = fmaxf(v1, 0.f);
                v2 = fmaxf(v2, 0.f); v3 = fmaxf(v3, 0.f);
            }
            float2 r0 = make_float2(v0, v1);
            float2 r1 = make_float2(v2, v3);
            *reinterpret_cast<float2*>(&Cout[(size_t)row * N + col]) = r0;
            *reinterpret_cast<float2*>(&Cout[(size_t)(row + 8) * N + col]) = r1;
        }
    }
}

__global__ __launch_bounds__(256, 2) void gemm1_kernel(
    const float* __restrict__ w1, const float* __restrict__ b1)
{
    int e = blockIdx.z;
    gemm_core<CAP, FF, D_MODEL, true>(
        d_xin + (size_t)e * CAP * D_MODEL,
        w1 + (size_t)e * D_MODEL * FF,
        b1 + (size_t)e * FF,
        d_h + (size_t)e * CAP * FF);
}

__global__ __launch_bounds__(256, 2) void gemm2_kernel(
    const float* __restrict__ w2, const float* __restrict__ b2)
{
    int e = blockIdx.z;
    gemm_core<CAP, D_MODEL, FF, false>(
        d_h + (size_t)e * CAP * FF,
        w2 + (size_t)e * FF * D_MODEL,
        b2 + (size_t)e * D_MODEL,
        d_eout + (size_t)e * CAP * D_MODEL);
}

// ---------------- 6) combine: per-token weighted sum of expert outputs ---------
__global__ __launch_bounds__(256) void combine_kernel(float* __restrict__ out)
{
    int t = blockIdx.x;
    int s0 = d_slot[2 * t], s1 = d_slot[2 * t + 1];
    float w0 = d_w[2 * t], w1 = d_w[2 * t + 1];
    int i = threadIdx.x * 4;
    float4 acc = make_float4(0.f, 0.f, 0.f, 0.f);
    if (s0 >= 0) {
        float4 a = *reinterpret_cast<const float4*>(
            &d_eout[(size_t)s0 * D_MODEL + i]);
        acc.x = w0 * a.x; acc.y = w0 * a.y; acc.z = w0 * a.z; acc.w = w0 * a.w;
    }
    if (s1 >= 0) {
        float4 b = *reinterpret_cast<const float4*>(
            &d_eout[(size_t)s1 * D_MODEL + i]);
        acc.x += w1 * b.x; acc.y += w1 * b.y; acc.z += w1 * b.z; acc.w += w1 * b.w;
    }
    *reinterpret_cast<float4*>(&out[(size_t)t * D_MODEL + i]) = acc;
}

// ---------------- launch ----------------
extern "C" void kernel_launch(void* const* d_in, const int* in_sizes, int n_in,
                              void* d_out, int out_size)
{
    const float* x      = (const float*)d_in[0];
    const float* gate_w = (const float*)d_in[1];
    const float* gate_b = (const float*)d_in[2];
    const float* w1     = (const float*)d_in[3];
    const float* b1     = (const float*)d_in[4];
    const float* w2     = (const float*)d_in[5];
    const float* b2     = (const float*)d_in[6];
    float* out          = (float*)d_out;

    gating_kernel<<<S_TOK / 8, 256>>>(x, gate_w, gate_b);
    route_kernel<<<1, 1024>>>();
    gather_kernel<<<NE * CAP, 256>>>(x);

    dim3 g1(FF / 64, CAP / 128, NE);       // 64 x 10 x 8
    gemm1_kernel<<<g1, 256>>>(w1, b1);
    dim3 g2(D_MODEL / 64, CAP / 128, NE);  // 16 x 10 x 8
    gemm2_kernel<<<g2, 256>>>(w2, b2);

    combine_kernel<<<S_TOK, 256>>>(out);
}

// round 9
// speedup vs baseline: 1.1322x; 1.1322x over previous
#include <cuda_runtime.h>
#include <cstdint>
#include <math.h>

#define D_MODEL 1024
#define FF      4096
#define NE      8
#define S_TOK   8192
#define CAP     1280   // int(1.25 * 8192 / 8)

// ---------------- scratch (device globals; no allocation allowed) ----------------
__device__ float d_xin [NE * CAP * D_MODEL];   // gathered expert inputs (tf32-rounded)
__device__ float d_h   [NE * CAP * FF];        // hidden activations (tf32-rounded)
__device__ float d_eout[NE * CAP * D_MODEL];   // expert outputs
__device__ float d_w1r [NE * D_MODEL * FF];    // tf32-rounded w1
__device__ float d_w2r [NE * FF * D_MODEL];    // tf32-rounded w2
__device__ int   d_idxbuf[NE * CAP];           // slot -> token
__device__ int   d_counts[NE];                 // per-expert filled slots (<= CAP)
__device__ int   d_slot [S_TOK * 2];           // (token,k) -> global slot or -1
__device__ float d_w    [S_TOK * 2];           // (token,k) -> normalized weight
__device__ int   d_top2 [S_TOK * 2];           // (token,k) -> expert id

// ---------------- helpers ----------------
__device__ __forceinline__ float to_tf32(float x) {
    float r;
    asm("cvt.rna.tf32.f32 %0, %1;" : "=f"(r) : "f"(x));
    return r;
}

__device__ __forceinline__ void cp_async16(void* smem_dst, const void* gmem_src) {
    uint32_t s = (uint32_t)__cvta_generic_to_shared(smem_dst);
    asm volatile("cp.async.cg.shared.global [%0], [%1], 16;\n" :: "r"(s), "l"(gmem_src));
}
#define CP_COMMIT()  asm volatile("cp.async.commit_group;\n" ::: "memory")
#define CP_WAIT(n)   asm volatile("cp.async.wait_group %0;\n" :: "n"(n) : "memory")

#define MMA_TF32(c, a, b)                                                        \
    asm volatile(                                                                \
        "mma.sync.aligned.m16n8k8.row.col.f32.tf32.tf32.f32 "                    \
        "{%0,%1,%2,%3},{%4,%5,%6,%7},{%8,%9},{%0,%1,%2,%3};\n"                   \
        : "+f"((c)[0]), "+f"((c)[1]), "+f"((c)[2]), "+f"((c)[3])                 \
        : "r"((a)[0]), "r"((a)[1]), "r"((a)[2]), "r"((a)[3]),                    \
          "r"((b)[0]), "r"((b)[1]))

// ---------------- 0) pre-round weights to tf32 (bandwidth-bound) ----------------
// blockIdx.y: 0 -> w1, 1 -> w2.  Each thread handles one float4.
__global__ __launch_bounds__(256) void round_w_kernel(
    const float* __restrict__ w1, const float* __restrict__ w2)
{
    size_t i = ((size_t)blockIdx.x * 256 + threadIdx.x) * 4;
    const float* src = blockIdx.y ? w2 : w1;
    float* dst       = blockIdx.y ? d_w2r : d_w1r;
    float4 v = *reinterpret_cast<const float4*>(src + i);
    v.x = to_tf32(v.x); v.y = to_tf32(v.y);
    v.z = to_tf32(v.z); v.w = to_tf32(v.w);
    *reinterpret_cast<float4*>(dst + i) = v;
}

// ---------------- 1) gating: logits -> top2 + normalized weights ----------------
// one warp per token, 8 tokens per 256-thread block
__global__ __launch_bounds__(256) void gating_kernel(
    const float* __restrict__ x, const float* __restrict__ gw,
    const float* __restrict__ gb)
{
    __shared__ float sgw[D_MODEL * NE];   // 32 KB
    for (int i = threadIdx.x; i < D_MODEL * NE; i += 256) sgw[i] = gw[i];
    __syncthreads();

    int wid = threadIdx.x >> 5, lane = threadIdx.x & 31;
    int t = blockIdx.x * 8 + wid;
    const float* xr = x + (size_t)t * D_MODEL;

    float acc[NE];
#pragma unroll
    for (int e = 0; e < NE; e++) acc[e] = 0.f;

    for (int j = lane; j < D_MODEL; j += 32) {
        float xv = xr[j];
#pragma unroll
        for (int e = 0; e < NE; e++) acc[e] += xv * sgw[j * NE + e];
    }
#pragma unroll
    for (int off = 16; off; off >>= 1) {
#pragma unroll
        for (int e = 0; e < NE; e++)
            acc[e] += __shfl_xor_sync(0xffffffffu, acc[e], off);
    }
    if (lane == 0) {
        float l0 = -1e30f, l1 = -1e30f;
        int e0 = 0, e1 = 0;
#pragma unroll
        for (int e = 0; e < NE; e++) {
            float l = acc[e] + gb[e];
            if (l > l0)      { l1 = l0; e1 = e0; l0 = l; e0 = e; }
            else if (l > l1) { l1 = l;  e1 = e; }
        }
        // normalized top-2 softmax weights: w0 = 1/(1+e^{l1-l0})
        float w0 = 1.0f / (1.0f + expf(l1 - l0));
        d_top2[2 * t]     = e0;
        d_top2[2 * t + 1] = e1;
        d_w[2 * t]     = w0;
        d_w[2 * t + 1] = 1.0f - w0;
    }
}

// ---------------- 2) routing: exact per-expert prefix count (token order) ------
// single block, 1024 threads, 8 chunks of 1024 tokens.
// 8 per-expert counters packed as 2x u64 of 4x16-bit lanes (max 1024/chunk fits).
__global__ __launch_bounds__(1024) void route_kernel()
{
    __shared__ unsigned long long wt0[32], wt1[32];
    __shared__ int base[NE];
    __shared__ unsigned long long ct0, ct1;

    int tid = threadIdx.x, lane = tid & 31, wid = tid >> 5;
    if (tid < NE) base[tid] = 0;
    __syncthreads();

    for (int chunk = 0; chunk < S_TOK / 1024; chunk++) {
        int t  = chunk * 1024 + tid;
        int e0 = d_top2[2 * t], e1 = d_top2[2 * t + 1];

        unsigned long long v0 = 0, v1 = 0;
        {
            unsigned long long inc = 1ull << ((e0 & 3) * 16);
            if (e0 < 4) v0 += inc; else v1 += inc;
        }
        {
            unsigned long long inc = 1ull << ((e1 & 3) * 16);
            if (e1 < 4) v0 += inc; else v1 += inc;
        }

        // warp inclusive scan
        unsigned long long p0 = v0, p1 = v1;
#pragma unroll
        for (int off = 1; off < 32; off <<= 1) {
            unsigned long long u0 = __shfl_up_sync(0xffffffffu, p0, off);
            unsigned long long u1 = __shfl_up_sync(0xffffffffu, p1, off);
            if (lane >= off) { p0 += u0; p1 += u1; }
        }
        if (lane == 31) { wt0[wid] = p0; wt1[wid] = p1; }
        __syncthreads();

        // warp 0 scans warp totals
        if (wid == 0) {
            unsigned long long q0 = wt0[lane], q1 = wt1[lane];
#pragma unroll
            for (int off = 1; off < 32; off <<= 1) {
                unsigned long long u0 = __shfl_up_sync(0xffffffffu, q0, off);
                unsigned long long u1 = __shfl_up_sync(0xffffffffu, q1, off);
                if (lane >= off) { q0 += u0; q1 += u1; }
            }
            wt0[lane] = q0; wt1[lane] = q1;
            if (lane == 31) { ct0 = q0; ct1 = q1; }
        }
        __syncthreads();

        unsigned long long ex0 = p0 - v0, ex1 = p1 - v1;  // exclusive within warp
        if (wid > 0) { ex0 += wt0[wid - 1]; ex1 += wt1[wid - 1]; }

#pragma unroll
        for (int k = 0; k < 2; k++) {
            int e = (k == 0) ? e0 : e1;
            unsigned long long ex = (e < 4) ? ex0 : ex1;
            int within = (int)((ex >> ((e & 3) * 16)) & 0xFFFFu);
            int pos = base[e] + within;
            int slot;
            if (pos < CAP) {
                slot = e * CAP + pos;
                d_idxbuf[slot] = t;
            } else {
                slot = -1;
            }
            d_slot[2 * t + k] = slot;
        }
        __syncthreads();
        if (tid < NE) {
            unsigned long long cv = (tid < 4) ? ct0 : ct1;
            base[tid] += (int)((cv >> ((tid & 3) * 16)) & 0xFFFFu);
        }
        __syncthreads();
    }
    if (threadIdx.x < NE)
        d_counts[threadIdx.x] = min(base[threadIdx.x], CAP);
}

// ---------------- 3) gather expert inputs (zero unfilled, tf32-rounded) --------
// one block per slot row, 256 threads x float4 = 1024 floats
__global__ __launch_bounds__(256) void gather_kernel(const float* __restrict__ x)
{
    int row = blockIdx.x;                 // 0 .. NE*CAP-1
    int e = row / CAP, c = row - e * CAP;
    float4 v = make_float4(0.f, 0.f, 0.f, 0.f);
    if (c < d_counts[e]) {
        int tok = d_idxbuf[row];
        v = *reinterpret_cast<const float4*>(
            &x[(size_t)tok * D_MODEL + threadIdx.x * 4]);
        v.x = to_tf32(v.x); v.y = to_tf32(v.y);
        v.z = to_tf32(v.z); v.w = to_tf32(v.w);
    }
    *reinterpret_cast<float4*>(
        &d_xin[(size_t)row * D_MODEL + threadIdx.x * 4]) = v;
}

// ---------------- 4/5) batched TF32 GEMM core, cp.async double-buffered --------
// C[M,N] = A[M,K] @ B[K,N] (+bias[N]) (+ReLU) (+tf32 round of output).
// Inputs MUST already be tf32-rounded. Tiles: 128x128x16, 8 warps (2m x 4n),
// warp tile 64x32 = 4x4 m16n8k8 mma per k-step, two k-steps per tile.
template <int N, int K, bool RELU, bool ROUND_OUT>
__device__ __forceinline__ void gemm_core(
    const float* __restrict__ A, const float* __restrict__ Bw,
    const float* __restrict__ bias, float* __restrict__ Cout)
{
    constexpr int BM = 128, BN = 128, BK = 16;
    constexpr int ASTR = BK + 4;   // 20: frag banks (gid*20+tig)%32 all distinct
    constexpr int BSTR = BN + 8;   // 136: frag banks (tig*8+gid+c)%32 all distinct
    __shared__ float As[2][BM][ASTR];   // 2 * 128*20*4 = 20.0 KB
    __shared__ float Bs[2][BK][BSTR];   // 2 * 16*136*4 = 17.4 KB

    const int tid = threadIdx.x;
    const int wid = tid >> 5, lane = tid & 31;
    const int gid = lane >> 2, tig = lane & 3;
    const int wm = (wid >> 2) * 64;    // warp m offset (0,64)
    const int wn = (wid & 3) * 32;     // warp n offset (0,32,64,96)
    const int m0 = blockIdx.y * BM;
    const int n0 = blockIdx.x * BN;

    // per-thread copy coordinates
    const int a_row0 = tid >> 2;            // 0..63   (chunk adds 64)
    const int a_col  = (tid & 3) * 4;       // 0,4,8,12
    const int b_row  = tid >> 4;            // 0..15
    const int b_col0 = (tid & 15) * 4;      // 0..60   (chunk adds 64)

    auto load_tile = [&](int buf, int k0) {
#pragma unroll
        for (int r = 0; r < 2; r++) {
            int row = a_row0 + r * 64;
            cp_async16(&As[buf][row][a_col],
                       &A[(size_t)(m0 + row) * K + k0 + a_col]);
        }
#pragma unroll
        for (int r = 0; r < 2; r++) {
            int col = b_col0 + r * 64;
            cp_async16(&Bs[buf][b_row][col],
                       &Bw[(size_t)(k0 + b_row) * N + n0 + col]);
        }
        CP_COMMIT();
    };

    float c[4][4][4];
#pragma unroll
    for (int mt = 0; mt < 4; mt++)
#pragma unroll
        for (int nt = 0; nt < 4; nt++)
#pragma unroll
            for (int i = 0; i < 4; i++) c[mt][nt][i] = 0.f;

    constexpr int NK = K / BK;
    load_tile(0, 0);

    for (int kt = 0; kt < NK; kt++) {
        const int buf = kt & 1;
        if (kt + 1 < NK) {
            load_tile(buf ^ 1, (kt + 1) * BK);
            CP_WAIT(1);
        } else {
            CP_WAIT(0);
        }
        __syncthreads();

#pragma unroll
        for (int kk = 0; kk < BK; kk += 8) {
            uint32_t a[4][4], b[4][2];
#pragma unroll
            for (int mt = 0; mt < 4; mt++) {
                int rb = wm + mt * 16;
                a[mt][0] = __float_as_uint(As[buf][rb + gid    ][kk + tig]);
                a[mt][1] = __float_as_uint(As[buf][rb + gid + 8][kk + tig]);
                a[mt][2] = __float_as_uint(As[buf][rb + gid    ][kk + tig + 4]);
                a[mt][3] = __float_as_uint(As[buf][rb + gid + 8][kk + tig + 4]);
            }
#pragma unroll
            for (int nt = 0; nt < 4; nt++) {
                int cb = wn + nt * 8;
                b[nt][0] = __float_as_uint(Bs[buf][kk + tig    ][cb + gid]);
                b[nt][1] = __float_as_uint(Bs[buf][kk + tig + 4][cb + gid]);
            }
#pragma unroll
            for (int mt = 0; mt < 4; mt++)
#pragma unroll
                for (int nt = 0; nt < 4; nt++)
                    MMA_TF32(c[mt][nt], a[mt], b[nt]);
        }
        __syncthreads();
    }

    // epilogue: +bias, optional relu, optional tf32 rounding, float2 stores
#pragma unroll
    for (int mt = 0; mt < 4; mt++) {
#pragma unroll
        for (int nt = 0; nt < 4; nt++) {
            int row = m0 + wm + mt * 16 + gid;
            int col = n0 + wn + nt * 8 + tig * 2;
            float b0v = bias[col], b1v = bias[col + 1];
            float v0 = c[mt][nt][0] + b0v;
            float v1 = c[mt][nt][1] + b1v;
            float v2 = c[mt][nt][2] + b0v;
            float v3 = c[mt][nt][3] + b1v;
            if (RELU) {
                v0 = fmaxf(v0, 0.f); v1 = fmaxf(v1, 0.f);
                v2 = fmaxf(v2, 0.f); v3 = fmaxf(v3, 0.f);
            }
            if (ROUND_OUT) {
                v0 = to_tf32(v0); v1 = to_tf32(v1);
                v2 = to_tf32(v2); v3 = to_tf32(v3);
            }
            float2 r0 = make_float2(v0, v1);
            float2 r1 = make_float2(v2, v3);
            *reinterpret_cast<float2*>(&Cout[(size_t)row * N + col]) = r0;
            *reinterpret_cast<float2*>(&Cout[(size_t)(row + 8) * N + col]) = r1;
        }
    }
}

__global__ __launch_bounds__(256, 2) void gemm1_kernel(const float* __restrict__ b1)
{
    int e = blockIdx.z;
    gemm_core<FF, D_MODEL, true, true>(
        d_xin + (size_t)e * CAP * D_MODEL,
        d_w1r + (size_t)e * D_MODEL * FF,
        b1 + (size_t)e * FF,
        d_h + (size_t)e * CAP * FF);
}

__global__ __launch_bounds__(256, 2) void gemm2_kernel(const float* __restrict__ b2)
{
    int e = blockIdx.z;
    gemm_core<D_MODEL, FF, false, false>(
        d_h + (size_t)e * CAP * FF,
        d_w2r + (size_t)e * FF * D_MODEL,
        b2 + (size_t)e * D_MODEL,
        d_eout + (size_t)e * CAP * D_MODEL);
}

// ---------------- 6) combine: per-token weighted sum of expert outputs ---------
__global__ __launch_bounds__(256) void combine_kernel(float* __restrict__ out)
{
    int t = blockIdx.x;
    int s0 = d_slot[2 * t], s1 = d_slot[2 * t + 1];
    float w0 = d_w[2 * t], w1 = d_w[2 * t + 1];
    int i = threadIdx.x * 4;
    float4 acc = make_float4(0.f, 0.f, 0.f, 0.f);
    if (s0 >= 0) {
        float4 a = *reinterpret_cast<const float4*>(
            &d_eout[(size_t)s0 * D_MODEL + i]);
        acc.x = w0 * a.x; acc.y = w0 * a.y; acc.z = w0 * a.z; acc.w = w0 * a.w;
    }
    if (s1 >= 0) {
        float4 b = *reinterpret_cast<const float4*>(
            &d_eout[(size_t)s1 * D_MODEL + i]);
        acc.x += w1 * b.x; acc.y += w1 * b.y; acc.z += w1 * b.z; acc.w += w1 * b.w;
    }
    *reinterpret_cast<float4*>(&out[(size_t)t * D_MODEL + i]) = acc;
}

// ---------------- launch ----------------
extern "C" void kernel_launch(void* const* d_in, const int* in_sizes, int n_in,
                              void* d_out, int out_size)
{
    const float* x      = (const float*)d_in[0];
    const float* gate_w = (const float*)d_in[1];
    const float* gate_b = (const float*)d_in[2];
    const float* w1     = (const float*)d_in[3];
    const float* b1     = (const float*)d_in[4];
    const float* w2     = (const float*)d_in[5];
    const float* b2     = (const float*)d_in[6];
    float* out          = (float*)d_out;

    // weights: NE*D_MODEL*FF = 33,554,432 elems = 8,388,608 float4 per array
    dim3 rw(8388608 / 256, 2);
    round_w_kernel<<<rw, 256>>>(w1, w2);

    gating_kernel<<<S_TOK / 8, 256>>>(x, gate_w, gate_b);
    route_kernel<<<1, 1024>>>();
    gather_kernel<<<NE * CAP, 256>>>(x);

    dim3 g1(FF / 128, CAP / 128, NE);       // 32 x 10 x 8
    gemm1_kernel<<<g1, 256>>>(b1);
    dim3 g2(D_MODEL / 128, CAP / 128, NE);  // 8 x 10 x 8
    gemm2_kernel<<<g2, 256>>>(b2);

    combine_kernel<<<S_TOK, 256>>>(out);
}